// round 9
// baseline (speedup 1.0000x reference)
#include <cuda_runtime.h>
#include <cuda_bf16.h>

// Problem constants
#define BB    32
#define NN    2048
#define KK    16
#define FIN   32
#define FOUT  64
#define TOTAL (BB * NN)          // 65536 nodes
#define ROW4  (FOUT / 4)         // 16 float4 per feature row
#define WR    384                // KNN half-window in sorted ranks
#define SPAN  (256 + 2 * (WR + 1))   // 1026 staged ranks per block

// Scratch (device globals: allocation-free rule).
__device__ float4 g_a[TOTAL * ROW4];   // a_i = x_i @ (W1 - W2) + b_edge
__device__ float4 g_c[TOTAL * ROW4];   // c_j = x_j @ W2
__device__ float4 g_s[TOTAL * ROW4];   // skip_i = relu(x_i @ W_nn + b_nn)
__device__ float4 g_spos[TOTAL];       // per-batch x-sorted (x,y,z,|p|^2)
__device__ int    g_sidx[TOTAL];       // sorted rank -> original global row
__device__ int    g_nb[TOTAL * KK];    // per original row: 16 neighbor rows

__device__ __forceinline__ float4 f4fma(float s, float4 w, float4 a) {
    a.x = __fmaf_rn(s, w.x, a.x);
    a.y = __fmaf_rn(s, w.y, a.y);
    a.z = __fmaf_rn(s, w.z, a.z);
    a.w = __fmaf_rn(s, w.w, a.w);
    return a;
}
__device__ __forceinline__ float4 f4max(float4 a, float4 b) {
    return make_float4(fmaxf(a.x, b.x), fmaxf(a.y, b.y),
                       fmaxf(a.z, b.z), fmaxf(a.w, b.w));
}

// Squared distance with a FIXED op sequence (all uses must agree bitwise).
__device__ __forceinline__ float dist2(float4 p, float4 q) {
    float dot = __fmaf_rn(p.x, q.x, __fmaf_rn(p.y, q.y, __fmul_rn(p.z, q.z)));
    return __fmaf_rn(-2.0f, dot, __fadd_rn(p.w, q.w));
}

// Sorted-16 insertion chain (caller gates with d < s[15]).
__device__ __forceinline__ void insert16(float (&s)[KK], float d) {
    float t = d;
#pragma unroll
    for (int q = 0; q < KK; q++) {
        float lo = fminf(s[q], t);
        t        = fmaxf(s[q], t);
        s[q]     = lo;
    }
}

// ---------------------------------------------------------------------------
// Kernel 0: per-batch bitonic sort of points by x. One block per batch.
// ---------------------------------------------------------------------------
__global__ __launch_bounds__(1024)
void sort_kernel(const float* __restrict__ pos)
{
    __shared__ float key[NN];
    __shared__ int   val[NN];

    int tid  = threadIdx.x;
    int base = blockIdx.x * NN;

    for (int t = tid; t < NN; t += 1024) {
        key[t] = pos[(base + t) * 3 + 0];
        val[t] = t;
    }

    for (int k = 2; k <= NN; k <<= 1) {
        for (int j = k >> 1; j > 0; j >>= 1) {
            __syncthreads();
#pragma unroll 1
            for (int t = tid; t < NN; t += 1024) {
                int ixj = t ^ j;
                if (ixj > t) {
                    bool up = ((t & k) == 0);
                    float a = key[t], b = key[ixj];
                    if ((a > b) == up) {
                        key[t] = b; key[ixj] = a;
                        int tv = val[t]; val[t] = val[ixj]; val[ixj] = tv;
                    }
                }
            }
        }
    }
    __syncthreads();

    for (int t = tid; t < NN; t += 1024) {
        int o = val[t];
        int g = base + o;
        float p0 = pos[g * 3 + 0];
        float p1 = pos[g * 3 + 1];
        float p2 = pos[g * 3 + 2];
        float sq = __fmaf_rn(p0, p0, __fmaf_rn(p1, p1, __fmul_rn(p2, p2)));
        g_spos[base + t] = make_float4(p0, p1, p2, sq);
        g_sidx[base + t] = g;
    }
}

// ---------------------------------------------------------------------------
// Kernel 1: per-node projections a, c, skip. One thread per node.
// ---------------------------------------------------------------------------
__global__ __launch_bounds__(128)
void proj_kernel(const float* __restrict__ x,
                 const float* __restrict__ W_edge,
                 const float* __restrict__ b_edge,
                 const float* __restrict__ W_nn,
                 const float* __restrict__ b_nn)
{
    __shared__ float sWd[FIN * FOUT];   // W1 - W2
    __shared__ float sW2[FIN * FOUT];   // W2
    __shared__ float sWn[FIN * FOUT];   // W_nn
    __shared__ float sbe[FOUT];
    __shared__ float sbn[FOUT];

    int tid = threadIdx.x;
    for (int t = tid; t < FIN * FOUT; t += 128) {
        float w1 = W_edge[t];
        float w2 = W_edge[FIN * FOUT + t];
        sWd[t] = w1 - w2;
        sW2[t] = w2;
        sWn[t] = W_nn[t];
    }
    if (tid < FOUT) { sbe[tid] = b_edge[tid]; sbn[tid] = b_nn[tid]; }
    __syncthreads();

    int node = blockIdx.x * 128 + tid;

    float xr[FIN];
    const float4* xp = (const float4*)(x + node * FIN);
#pragma unroll
    for (int q = 0; q < FIN / 4; q++) {
        float4 v = xp[q];
        xr[4 * q + 0] = v.x; xr[4 * q + 1] = v.y;
        xr[4 * q + 2] = v.z; xr[4 * q + 3] = v.w;
    }

    int rowb = node * ROW4;
#pragma unroll 1
    for (int fc = 0; fc < FOUT; fc += 4) {
        float4 aA = *(const float4*)&sbe[fc];
        float4 aC = make_float4(0.f, 0.f, 0.f, 0.f);
        float4 aS = *(const float4*)&sbn[fc];
#pragma unroll
        for (int r = 0; r < FIN; r++) {
            float xv = xr[r];
            aA = f4fma(xv, *(const float4*)&sWd[r * FOUT + fc], aA);
            aC = f4fma(xv, *(const float4*)&sW2[r * FOUT + fc], aC);
            aS = f4fma(xv, *(const float4*)&sWn[r * FOUT + fc], aS);
        }
        aS.x = fmaxf(aS.x, 0.f); aS.y = fmaxf(aS.y, 0.f);
        aS.z = fmaxf(aS.z, 0.f); aS.w = fmaxf(aS.w, 0.f);
        g_a[rowb + (fc >> 2)] = aA;
        g_c[rowb + (fc >> 2)] = aC;
        g_s[rowb + (fc >> 2)] = aS;
    }
}

// ---------------------------------------------------------------------------
// Kernel 2: exact KNN, x-sorted fixed-window scan from smem.
// One thread per point. Block owns 256 consecutive sorted ranks [s0, s0+256);
// the union window [s0-385, s0+640] (1026 entries, OOB -> sentinel) is staged
// in smem. Thread tid (rank r = s0+tid) scans ranks r+-1..r+-WR NEAR-TO-FAR:
//   smem index for rank r+D is (tid + 385 + D); self (D=0) never visited.
// Pass 1: exact sorted-16 distances (gated FMNMX insertion chain).
// Guard: if the nearest EXCLUDED rank on either side could still beat s15
// (dx^2 <= s15 + 1e-3, conservative vs <1e-4 fp deviation of dist2), the lane
// falls back to a full exact 2048-scan  -> result is exact regardless of WR.
// Pass 2: recompute d bitwise-identically, collect orig ids with d <= t16
// (cap 16). Multiset equals reference top_k's; order is irrelevant to max.
// ---------------------------------------------------------------------------
__global__ __launch_bounds__(256)
void knn_kernel()
{
    __shared__ float4 sp[SPAN];
    __shared__ int    ssid[SPAN];

    int tid   = threadIdx.x;
    int batch = blockIdx.x >> 3;
    int s0    = (blockIdx.x & 7) << 8;
    int base  = batch * NN;

    for (int i = tid; i < SPAN; i += 256) {
        int rank = s0 + i - (WR + 1);
        bool ok = (rank >= 0) && (rank < NN);
        int rc = ok ? rank : 0;
        float4 v = g_spos[base + rc];
        int   id = g_sidx[base + rc];
        if (!ok) { v = make_float4(0.f, 0.f, 0.f, 3.0e38f); id = 0; }
        sp[i]   = v;
        ssid[i] = id;
    }
    __syncthreads();

    int   c  = tid + WR + 1;        // smem index of self
    float4 pi = sp[c];
    int   r  = s0 + tid;            // rank within batch

    float s[KK];
#pragma unroll
    for (int q = 0; q < KK; q++) s[q] = 3.0e38f;

    // ---- Pass 1: near-to-far, both sides ----
#pragma unroll 4
    for (int it = 1; it <= WR; it++) {
        float d = dist2(pi, sp[c - it]);
        if (d < s[KK - 1]) insert16(s, d);
    }
#pragma unroll 4
    for (int it = 1; it <= WR; it++) {
        float d = dist2(pi, sp[c + it]);
        if (d < s[KK - 1]) insert16(s, d);
    }

    // ---- Exactness guard ----
    bool bad = false;
    if (r >= WR + 1) {                       // nearest excluded left rank
        float dx = pi.x - sp[tid].x;         // index tid == c - (WR+1)
        if (!(__fmul_rn(dx, dx) > s[KK - 1] + 1e-3f)) bad = true;
    }
    if (r + WR + 1 < NN) {                   // nearest excluded right rank
        float dx = sp[c + WR + 1].x - pi.x;
        if (!(__fmul_rn(dx, dx) > s[KK - 1] + 1e-3f)) bad = true;
    }
    if (bad) {                               // rare exact fallback (global)
#pragma unroll
        for (int q = 0; q < KK; q++) s[q] = 3.0e38f;
        for (int j = 0; j < NN; j++) {
            if (j == r) continue;
            float d = dist2(pi, g_spos[base + j]);
            if (d < s[KK - 1]) insert16(s, d);
        }
    }
    float t16 = s[KK - 1];

    // ---- Pass 2: collect neighbor original ids ----
    int orig_i = ssid[c];
    int nbb = orig_i * KK;
    int cnt = 0;
    if (!bad) {
#pragma unroll 4
        for (int it = 1; it <= WR; it++) {
            float d = dist2(pi, sp[c - it]);
            if (d <= t16) {
                if (cnt < KK) g_nb[nbb + cnt] = ssid[c - it];
                cnt++;
            }
        }
#pragma unroll 4
        for (int it = 1; it <= WR; it++) {
            float d = dist2(pi, sp[c + it]);
            if (d <= t16) {
                if (cnt < KK) g_nb[nbb + cnt] = ssid[c + it];
                cnt++;
            }
        }
    } else {
        for (int j = 0; j < NN; j++) {
            if (j == r) continue;
            float d = dist2(pi, g_spos[base + j]);
            if (d <= t16) {
                if (cnt < KK) g_nb[nbb + cnt] = g_sidx[base + j];
                cnt++;
            }
        }
    }
}

// ---------------------------------------------------------------------------
// Kernel 3: aggregation, coalesced. 16 lanes per node; lane q owns output
// float4 q. Neighbor ids broadcast within the 16-lane group via shfl so each
// g_c load instruction reads one 256B row segment (coalesced).
// ---------------------------------------------------------------------------
__global__ __launch_bounds__(256)
void agg_kernel(float4* __restrict__ out)
{
    int g = blockIdx.x * 256 + threadIdx.x;   // TOTAL*16 threads
    int i = g >> 4;                           // node
    int q = g & 15;                           // float4 lane within row

    int myid = g_nb[i * KK + q];              // lane q holds neighbor q (coalesced)

    float4 m = make_float4(-3e38f, -3e38f, -3e38f, -3e38f);
#pragma unroll
    for (int k = 0; k < KK; k++) {
        int idk = __shfl_sync(0xffffffffu, myid, k, 16);
        m = f4max(m, g_c[idk * ROW4 + q]);
    }

    int irow = i * ROW4 + q;
    float4 a  = g_a[irow];
    float4 sk = g_s[irow];
    float4 o;
    o.x = fmaxf(a.x + m.x, 0.f) + sk.x;
    o.y = fmaxf(a.y + m.y, 0.f) + sk.y;
    o.z = fmaxf(a.z + m.z, 0.f) + sk.z;
    o.w = fmaxf(a.w + m.w, 0.f) + sk.w;
    out[irow] = o;
}

// ---------------------------------------------------------------------------
// Inputs (metadata order): x, pos, W_edge, b_edge, W_nn, b_nn, batch(unused)
// Output: float32 [65536, 64]
// ---------------------------------------------------------------------------
extern "C" void kernel_launch(void* const* d_in, const int* in_sizes, int n_in,
                              void* d_out, int out_size)
{
    const float* x      = (const float*)d_in[0];
    const float* pos    = (const float*)d_in[1];
    const float* W_edge = (const float*)d_in[2];
    const float* b_edge = (const float*)d_in[3];
    const float* W_nn   = (const float*)d_in[4];
    const float* b_nn   = (const float*)d_in[5];

    sort_kernel<<<BB, 1024>>>(pos);
    proj_kernel<<<TOTAL / 128, 128>>>(x, W_edge, b_edge, W_nn, b_nn);
    knn_kernel<<<TOTAL / 256, 256>>>();
    agg_kernel<<<TOTAL * 16 / 256, 256>>>((float4*)d_out);
}

// round 11
// speedup vs baseline: 2.0233x; 2.0233x over previous
#include <cuda_runtime.h>
#include <cuda_bf16.h>

// Problem constants
#define BB    32
#define NN    2048
#define KK    16
#define FIN   32
#define FOUT  64
#define TOTAL (BB * NN)          // 65536 nodes
#define ROW4  (FOUT / 4)         // 16 float4 per feature row
#define FULLM 0xffffffffu

// Scratch (device globals: allocation-free rule).
__device__ float4 g_a[TOTAL * ROW4];   // a_i = x_i @ (W1 - W2) + b_edge
__device__ float4 g_c[TOTAL * ROW4];   // c_j = x_j @ W2
__device__ float4 g_s[TOTAL * ROW4];   // skip_i = relu(x_i @ W_nn + b_nn)
__device__ float4 g_spos[TOTAL];       // per-batch x-sorted (x,y,z,|p|^2)
__device__ int    g_sidx[TOTAL];       // sorted rank -> original global row
__device__ int    g_nb[TOTAL * KK];    // per original row: 16 neighbor rows

__device__ __forceinline__ float4 f4fma(float s, float4 w, float4 a) {
    a.x = __fmaf_rn(s, w.x, a.x);
    a.y = __fmaf_rn(s, w.y, a.y);
    a.z = __fmaf_rn(s, w.z, a.z);
    a.w = __fmaf_rn(s, w.w, a.w);
    return a;
}
__device__ __forceinline__ float4 f4max(float4 a, float4 b) {
    return make_float4(fmaxf(a.x, b.x), fmaxf(a.y, b.y),
                       fmaxf(a.z, b.z), fmaxf(a.w, b.w));
}

// Squared distance with a FIXED op sequence (all uses must agree bitwise).
__device__ __forceinline__ float dist2(float4 p, float4 q) {
    float dot = __fmaf_rn(p.x, q.x, __fmaf_rn(p.y, q.y, __fmul_rn(p.z, q.z)));
    return __fmaf_rn(-2.0f, dot, __fadd_rn(p.w, q.w));
}

// Full warp bitonic sort, ascending across lanes (classic xor-shuffle network).
__device__ __forceinline__ float warp_sort_asc(float v, int lane) {
#pragma unroll
    for (int k = 2; k <= 32; k <<= 1) {
#pragma unroll
        for (int j = k >> 1; j > 0; j >>= 1) {
            float o = __shfl_xor_sync(FULLM, v, j);
            bool up    = ((lane & k) == 0);
            bool lower = ((lane & j) == 0);
            float mn = fminf(v, o), mx = fmaxf(v, o);
            v = (up == lower) ? mn : mx;
        }
    }
    return v;
}

// Cleanup of a bitonic 32-sequence to ascending (bitonic merge network).
__device__ __forceinline__ float warp_bitonic_merge_asc(float v, int lane) {
#pragma unroll
    for (int j = 16; j >= 1; j >>= 1) {
        float o = __shfl_xor_sync(FULLM, v, j);
        bool lower = ((lane & j) == 0);
        float mn = fminf(v, o), mx = fmaxf(v, o);
        v = lower ? mn : mx;
    }
    return v;
}

// ---------------------------------------------------------------------------
// Kernel 0: per-batch bitonic sort of points by x. One block per batch.
// ---------------------------------------------------------------------------
__global__ __launch_bounds__(1024)
void sort_kernel(const float* __restrict__ pos)
{
    __shared__ float key[NN];
    __shared__ int   val[NN];

    int tid  = threadIdx.x;
    int base = blockIdx.x * NN;

    for (int t = tid; t < NN; t += 1024) {
        key[t] = pos[(base + t) * 3 + 0];
        val[t] = t;
    }

    for (int k = 2; k <= NN; k <<= 1) {
        for (int j = k >> 1; j > 0; j >>= 1) {
            __syncthreads();
#pragma unroll 1
            for (int t = tid; t < NN; t += 1024) {
                int ixj = t ^ j;
                if (ixj > t) {
                    bool up = ((t & k) == 0);
                    float a = key[t], b = key[ixj];
                    if ((a > b) == up) {
                        key[t] = b; key[ixj] = a;
                        int tv = val[t]; val[t] = val[ixj]; val[ixj] = tv;
                    }
                }
            }
        }
    }
    __syncthreads();

    for (int t = tid; t < NN; t += 1024) {
        int o = val[t];
        int g = base + o;
        float p0 = pos[g * 3 + 0];
        float p1 = pos[g * 3 + 1];
        float p2 = pos[g * 3 + 2];
        float sq = __fmaf_rn(p0, p0, __fmaf_rn(p1, p1, __fmul_rn(p2, p2)));
        g_spos[base + t] = make_float4(p0, p1, p2, sq);
        g_sidx[base + t] = g;
    }
}

// ---------------------------------------------------------------------------
// Kernel 1: per-node projections a, c, skip. One thread per node.
// ---------------------------------------------------------------------------
__global__ __launch_bounds__(256)
void proj_kernel(const float* __restrict__ x,
                 const float* __restrict__ W_edge,
                 const float* __restrict__ b_edge,
                 const float* __restrict__ W_nn,
                 const float* __restrict__ b_nn)
{
    __shared__ float sWd[FIN * FOUT];   // W1 - W2
    __shared__ float sW2[FIN * FOUT];   // W2
    __shared__ float sWn[FIN * FOUT];   // W_nn
    __shared__ float sbe[FOUT];
    __shared__ float sbn[FOUT];

    int tid = threadIdx.x;
    for (int t = tid; t < FIN * FOUT; t += 256) {
        float w1 = W_edge[t];
        float w2 = W_edge[FIN * FOUT + t];
        sWd[t] = w1 - w2;
        sW2[t] = w2;
        sWn[t] = W_nn[t];
    }
    if (tid < FOUT) { sbe[tid] = b_edge[tid]; sbn[tid] = b_nn[tid]; }
    __syncthreads();

    int node = blockIdx.x * 256 + tid;

    float xr[FIN];
    const float4* xp = (const float4*)(x + node * FIN);
#pragma unroll
    for (int q = 0; q < FIN / 4; q++) {
        float4 v = xp[q];
        xr[4 * q + 0] = v.x; xr[4 * q + 1] = v.y;
        xr[4 * q + 2] = v.z; xr[4 * q + 3] = v.w;
    }

    int rowb = node * ROW4;
#pragma unroll 1
    for (int fc = 0; fc < FOUT; fc += 4) {
        float4 aA = *(const float4*)&sbe[fc];
        float4 aC = make_float4(0.f, 0.f, 0.f, 0.f);
        float4 aS = *(const float4*)&sbn[fc];
#pragma unroll
        for (int r = 0; r < FIN; r++) {
            float xv = xr[r];
            aA = f4fma(xv, *(const float4*)&sWd[r * FOUT + fc], aA);
            aC = f4fma(xv, *(const float4*)&sW2[r * FOUT + fc], aC);
            aS = f4fma(xv, *(const float4*)&sWn[r * FOUT + fc], aS);
        }
        aS.x = fmaxf(aS.x, 0.f); aS.y = fmaxf(aS.y, 0.f);
        aS.z = fmaxf(aS.z, 0.f); aS.w = fmaxf(aS.w, 0.f);
        g_a[rowb + (fc >> 2)] = aA;
        g_c[rowb + (fc >> 2)] = aC;
        g_s[rowb + (fc >> 2)] = aS;
    }
}

// ---------------------------------------------------------------------------
// Kernel 2: exact KNN, warp-cooperative. ONE WARP PER POINT.
// The 32 lanes evaluate 32 consecutive x-sorted ranks per batch (coalesced
// LDG.128, warp-uniform control flow -> zero divergence). Warp holds a
// sorted-32 candidate list L (1 float/lane, ascending by lane). Per batch:
//   gate:   skip merge if no d < L[15] (ballot)
//   merge:  warp bitonic sort of the 32 distances + halving-min + cleanup
//   exit:   farthest dx^2 in batch > L[15] + 1e-3  (sound: x-sorted; margin
//           >> fp deviation of the fixed dist2 sequence; L[15]=inf until 16
//           candidates seen, so never exits early)
// Scans right (ascending rank) then left. t16 = L[15] = exact 16th-smallest.
// Pass 2 rescans with identical dist2, collects ids with d <= t16 via
// ballot+popc compaction (cap 16) -> multiset equals reference top_k's.
// ---------------------------------------------------------------------------
__global__ __launch_bounds__(256)
void knn_kernel()
{
    int gw   = (blockIdx.x * 256 + threadIdx.x) >> 5;  // point id 0..65535
    int lane = threadIdx.x & 31;
    int bt   = gw >> 11;
    int base = bt * NN;
    int r    = gw & (NN - 1);

    float4 pi = g_spos[base + r];

    float L = 3.0e38f;

#pragma unroll 1
    for (int dir = 0; dir < 2; dir++) {
#pragma unroll 1
        for (int b = 0; ; b++) {
            int j = (dir == 0) ? (r + 1 + b * 32 + lane)
                               : (r - 1 - b * 32 - lane);
            bool ok = (j >= 0) && (j < NN);
            int jc = ok ? j : r;
            float4 q4 = g_spos[base + jc];
            float d = ok ? dist2(pi, q4) : 3.0e38f;

            float l15 = __shfl_sync(FULLM, L, 15);
            unsigned m = __ballot_sync(FULLM, d < l15);
            if (m) {
                float B = warp_sort_asc(d, lane);
                float Brev = __shfl_xor_sync(FULLM, B, 31);     // descending
                float v = fminf(L, Brev);                       // bitonic, 32 smallest
                L = warp_bitonic_merge_asc(v, lane);
            }

            bool oobany = __any_sync(FULLM, !ok);
            float dx  = (dir == 0) ? (q4.x - pi.x) : (pi.x - q4.x);
            float dxf = __shfl_sync(FULLM, dx, 31);             // farthest in batch
            float l15b = __shfl_sync(FULLM, L, 15);
            if (oobany || __fmul_rn(dxf, dxf) > l15b + 1e-3f) break;
        }
    }

    float t16 = __shfl_sync(FULLM, L, 15);
    int orig_i = __ldg(&g_sidx[base + r]);
    int nbb = orig_i * KK;
    int cnt = 0;

#pragma unroll 1
    for (int dir = 0; dir < 2 && cnt < KK; dir++) {
#pragma unroll 1
        for (int b = 0; ; b++) {
            int j = (dir == 0) ? (r + 1 + b * 32 + lane)
                               : (r - 1 - b * 32 - lane);
            bool ok = (j >= 0) && (j < NN);
            int jc = ok ? j : r;
            float4 q4 = g_spos[base + jc];
            float d = ok ? dist2(pi, q4) : 3.0e38f;

            bool hit = ok && (d <= t16);
            unsigned m = __ballot_sync(FULLM, hit);
            int off = cnt + __popc(m & ((1u << lane) - 1u));
            if (hit && off < KK) g_nb[nbb + off] = g_sidx[base + j];
            cnt += __popc(m);

            bool oobany = __any_sync(FULLM, !ok);
            float dx  = (dir == 0) ? (q4.x - pi.x) : (pi.x - q4.x);
            float dxf = __shfl_sync(FULLM, dx, 31);
            if (oobany || cnt >= KK ||
                __fmul_rn(dxf, dxf) > t16 + 1e-3f) break;
        }
    }
}

// ---------------------------------------------------------------------------
// Kernel 3: aggregation, coalesced. 16 lanes per node; lane q owns output
// float4 q. Neighbor ids broadcast within the 16-lane group via shfl so each
// g_c load instruction reads one 256B row segment (coalesced).
// ---------------------------------------------------------------------------
__global__ __launch_bounds__(256)
void agg_kernel(float4* __restrict__ out)
{
    int g = blockIdx.x * 256 + threadIdx.x;   // TOTAL*16 threads
    int i = g >> 4;                           // node
    int q = g & 15;                           // float4 lane within row

    int myid = g_nb[i * KK + q];              // lane q holds neighbor q (coalesced)

    float4 m = make_float4(-3e38f, -3e38f, -3e38f, -3e38f);
#pragma unroll
    for (int k = 0; k < KK; k++) {
        int idk = __shfl_sync(FULLM, myid, k, 16);
        m = f4max(m, g_c[idk * ROW4 + q]);
    }

    int irow = i * ROW4 + q;
    float4 a  = g_a[irow];
    float4 sk = g_s[irow];
    float4 o;
    o.x = fmaxf(a.x + m.x, 0.f) + sk.x;
    o.y = fmaxf(a.y + m.y, 0.f) + sk.y;
    o.z = fmaxf(a.z + m.z, 0.f) + sk.z;
    o.w = fmaxf(a.w + m.w, 0.f) + sk.w;
    out[irow] = o;
}

// ---------------------------------------------------------------------------
// Inputs (metadata order): x, pos, W_edge, b_edge, W_nn, b_nn, batch(unused)
// Output: float32 [65536, 64]
// ---------------------------------------------------------------------------
extern "C" void kernel_launch(void* const* d_in, const int* in_sizes, int n_in,
                              void* d_out, int out_size)
{
    const float* x      = (const float*)d_in[0];
    const float* pos    = (const float*)d_in[1];
    const float* W_edge = (const float*)d_in[2];
    const float* b_edge = (const float*)d_in[3];
    const float* W_nn   = (const float*)d_in[4];
    const float* b_nn   = (const float*)d_in[5];

    sort_kernel<<<BB, 1024>>>(pos);
    proj_kernel<<<TOTAL / 256, 256>>>(x, W_edge, b_edge, W_nn, b_nn);
    knn_kernel<<<TOTAL * 32 / 256, 256>>>();
    agg_kernel<<<TOTAL * 16 / 256, 256>>>((float4*)d_out);
}